// round 11
// baseline (speedup 1.0000x reference)
#include <cuda_runtime.h>

// VolumeRotation: B=8, C=16, S=64 — round 10.
// Two independent 512-thread blocks per SM (__launch_bounds__(512,2)), each
// owning a full 16^3 tile + single-buffered 29x29x32f window (107648 B).
// Iso-traffic with R8; sibling block hides fill latency. SPT=8 with
// compressed per-sample state (pk + tx/ty/tz), weights recomputed per channel.

#define SB 64
#define CB 16
#define S3 (SB*SB*SB)
#define TT 16
#define NTHR 512
#define SPT 8                     // 4096 voxels / 512 threads
#define WWN 29                    // y,z window cells
#define NROWS (WWN*WWN)           // 841
#define WIN_BYTES (NROWS*128)     // 107648
#define SLOTS 14                  // rows r0 + 64*j, j=0..13 (64*14=896>=841)

__device__ __forceinline__ void sample_pos(
    float r00, float r01, float r02,
    float r10, float r11, float r12,
    float r20, float r21, float r22,
    int x, int y, int z,
    float& fx, float& fy, float& fz)
{
    const float sc = 2.0f / 63.0f;
    float bx = fmaf((float)x, sc, -1.0f);
    float by = fmaf((float)y, sc, -1.0f);
    float bz = fmaf((float)z, sc, -1.0f);
    float gx = fmaf(r00, bx, fmaf(r10, by, r20 * bz));
    float gy = fmaf(r01, bx, fmaf(r11, by, r21 * bz));
    float gz = fmaf(r02, bx, fmaf(r12, by, r22 * bz));
    fx = fmaf(gx, 32.0f, 31.5f);
    fy = fmaf(gy, 32.0f, 31.5f);
    fz = fmaf(gz, 32.0f, 31.5f);
}

__global__ __launch_bounds__(NTHR, 2)
void volrot_kernel(const float* __restrict__ vol,
                   const float* __restrict__ rot,
                   float* __restrict__ out)
{
    extern __shared__ float smemf[];
    const char* wb = (const char*)smemf;
    unsigned su = (unsigned)__cvta_generic_to_shared(smemf);

    int tid = threadIdx.x;
    int blk = blockIdx.x;
    int b = blk >> 6;                 // 64 tiles per batch
    int t = blk & 63;
    int oz = (t >> 4) * TT;
    int oy = ((t >> 2) & 3) * TT;
    int ox = (t & 3) * TT;

    const float* R = rot + b * 9;
    float r00 = __ldg(R+0), r01 = __ldg(R+1), r02 = __ldg(R+2);
    float r10 = __ldg(R+3), r11 = __ldg(R+4), r12 = __ldg(R+5);
    float r20 = __ldg(R+6), r21 = __ldg(R+7), r22 = __ldg(R+8);

    // min/max sample coords over the 8 tile corners (affine => hull)
    float mnx = 1e30f, mny = 1e30f, mnz = 1e30f;
    float mxx = -1e30f, mxy = -1e30f, mxz = -1e30f;
    #pragma unroll
    for (int k = 0; k < 8; k++) {
        int cx = ox + ((k & 1) ? TT - 1 : 0);
        int cy = oy + ((k & 2) ? TT - 1 : 0);
        int cz = oz + ((k & 4) ? TT - 1 : 0);
        float fx, fy, fz;
        sample_pos(r00,r01,r02,r10,r11,r12,r20,r21,r22, cx, cy, cz, fx, fy, fz);
        mnx = fminf(mnx, fx); mny = fminf(mny, fy); mnz = fminf(mnz, fz);
        mxx = fmaxf(mxx, fx); mxy = fmaxf(mxy, fy); mxz = fmaxf(mxz, fz);
    }
    int bax = ((int)floorf(mnx)) & ~3;
    int bay = (int)floorf(mny);
    int baz = (int)floorf(mnz);
    int exMax = ((int)floorf(mxx)) + 1 - bax;
    int eyMax = ((int)floorf(mxy)) + 1 - bay;
    int ezMax = ((int)floorf(mxz)) + 1 - baz;

    // ---- staging masks (channel-invariant): quad = (row = r0 + 64j, xq)
    int xq = tid & 7;
    int r0 = tid >> 3;                // 0..63
    int gxq = bax + (xq << 2);
    int wz_i = r0 / WWN;              // 0..2
    int wy_i = r0 - wz_i * WWN;
    unsigned need = 0, inb = 0;
    {
        int wy = wy_i, wz = wz_i;
        #pragma unroll
        for (int j = 0; j < SLOTS; j++) {
            int rowid = r0 + j * 64;
            if (rowid < NROWS) {
                bool nd = ((xq << 2) <= exMax) & (wy <= eyMax) & (wz <= ezMax);
                int gy = bay + wy, gz = baz + wz;
                bool ok = ((unsigned)gxq <= (unsigned)(SB - 4)) &
                          ((unsigned)gy < (unsigned)SB) &
                          ((unsigned)gz < (unsigned)SB);
                if (nd) need |= (1u << j);
                if (ok) inb  |= (1u << j);
            }
            wy += 6; wz += 2;                    // +64 rows = +2*29 + 6
            if (wy >= WWN) { wy -= WWN; wz++; }
        }
    }
    unsigned sidx0 = (unsigned)(r0 * 128 + ((xq ^ (r0 & 7)) << 4));

    // ---- per-sample channel-invariant state: pk + tx/ty/tz (4 regs/sample)
    unsigned pk[SPT];
    float txr[SPT], tyr[SPT], tzr[SPT];
    unsigned obyte0 = 0;

    #pragma unroll
    for (int s = 0; s < SPT; s++) {
        int v = tid + s * NTHR;           // 0..4095
        int lx = v & 15, ly = (v >> 4) & 15, lz = v >> 8;
        int x = ox + lx, y = oy + ly, z = oz + lz;
        float fx, fy, fz;
        sample_pos(r00,r01,r02,r10,r11,r12,r20,r21,r22, x, y, z, fx, fy, fz);
        float x0f = floorf(fx), y0f = floorf(fy), z0f = floorf(fz);
        txr[s] = fx - x0f; tyr[s] = fy - y0f; tzr[s] = fz - z0f;
        int x0 = (int)x0f, y0 = (int)y0f, z0 = (int)z0f;

        unsigned vb = 0;
        if ((unsigned)x0       < (unsigned)SB) vb |= 1u << 20;
        if ((unsigned)(x0 + 1) < (unsigned)SB) vb |= 1u << 21;
        if ((unsigned)y0       < (unsigned)SB) vb |= 1u << 22;
        if ((unsigned)(y0 + 1) < (unsigned)SB) vb |= 1u << 23;
        if ((unsigned)z0       < (unsigned)SB) vb |= 1u << 24;
        if ((unsigned)(z0 + 1) < (unsigned)SB) vb |= 1u << 25;

        int wx0 = min(max(x0 - bax, 0), 30);
        int wy0 = min(max(y0 - bay, 0), WWN - 2);
        int wz0 = min(max(z0 - baz, 0), WWN - 2);
        unsigned rowid = (unsigned)(wz0 * WWN + wy0);        // <= 810
        int xa = wx0, xb = wx0 + 1;
        unsigned ca0q = (unsigned)(((xa >> 2) << 2) | (xa & 3));   // ca0>>2
        unsigned ca1q = (unsigned)(((xb >> 2) << 2) | (xb & 3));
        pk[s] = rowid | (ca0q << 10) | (ca1q << 15) | vb;
        if (s == 0) obyte0 = (unsigned)((((z * SB) + y) * SB + x) * 4);
    }

    const char* srcb = (const char*)vol + (size_t)b * CB * S3 * 4;
    char*       dstb = (char*)out       + (size_t)b * CB * S3 * 4;

    #pragma unroll 1
    for (int c = 0; c < CB; c++) {
        // ---- fill channel c window
        {
            const char* g = srcb + (size_t)c * S3 * 4;
            int wy = wy_i, wz = wz_i;
            #pragma unroll
            for (int j = 0; j < SLOTS; j++) {
                if ((need >> j) & 1u) {
                    int gy = bay + wy, gz = baz + wz;
                    unsigned ok = (inb >> j) & 1u;
                    unsigned go = ok ? (unsigned)((((gz * SB) + gy) * SB + gxq) * 4) : 0u;
                    unsigned sz = ok << 4;
                    asm volatile("cp.async.cg.shared.global [%0], [%1], 16, %2;"
                        :: "r"(su + sidx0 + (unsigned)(j * 8192)),
                           "l"(g + go), "r"(sz) : "memory");
                }
                wy += 6; wz += 2;
                if (wy >= WWN) { wy -= WWN; wz++; }
            }
            asm volatile("cp.async.commit_group;" ::: "memory");
        }
        asm volatile("cp.async.wait_group 0;" ::: "memory");
        __syncthreads();             // fill visible to all warps

        // ---- gather channel c
        char* dc = dstb + (size_t)c * S3 * 4 + obyte0;
        #pragma unroll
        for (int s = 0; s < SPT; s++) {
            unsigned p = pk[s];
            unsigned rowid = p & 1023u;
            unsigned ca0 = ((p >> 10) & 31u) << 2;
            unsigned ca1 = ((p >> 15) & 31u) << 2;
            float tx = txr[s], ty = tyr[s], tz = tzr[s];
            float ex0 = (p & (1u << 20)) ? (1.0f - tx) : 0.0f;
            float ex1 = (p & (1u << 21)) ? tx          : 0.0f;
            float wy0 = (p & (1u << 22)) ? (1.0f - ty) : 0.0f;
            float wy1 = (p & (1u << 23)) ? ty          : 0.0f;
            float wz0 = (p & (1u << 24)) ? (1.0f - tz) : 0.0f;
            float wz1 = (p & (1u << 25)) ? tz          : 0.0f;
            float wp0 = wy0 * wz0, wp1 = wy1 * wz0;
            float wp2 = wy0 * wz1, wp3 = wy1 * wz1;

            unsigned rk0 = rowid * 128 + ((rowid & 7) << 4);
            unsigned rr1 = rowid + 1;
            unsigned rk1 = rr1 * 128 + ((rr1 & 7) << 4);
            unsigned rr2 = rowid + WWN;
            unsigned rk2 = rr2 * 128 + ((rr2 & 7) << 4);
            unsigned rr3 = rowid + WWN + 1;
            unsigned rk3 = rr3 * 128 + ((rr3 & 7) << 4);

            float v00 = *(const float*)(wb + (rk0 ^ ca0));
            float v01 = *(const float*)(wb + (rk0 ^ ca1));
            float v10 = *(const float*)(wb + (rk1 ^ ca0));
            float v11 = *(const float*)(wb + (rk1 ^ ca1));
            float v20 = *(const float*)(wb + (rk2 ^ ca0));
            float v21 = *(const float*)(wb + (rk2 ^ ca1));
            float v30 = *(const float*)(wb + (rk3 ^ ca0));
            float v31 = *(const float*)(wb + (rk3 ^ ca1));

            float s0 = fmaf(ex0, v00, ex1 * v01);
            float s1 = fmaf(ex0, v10, ex1 * v11);
            float s2 = fmaf(ex0, v20, ex1 * v21);
            float s3 = fmaf(ex0, v30, ex1 * v31);
            float acc = wp0 * s0;
            acc = fmaf(wp1, s1, acc);
            acc = fmaf(wp2, s2, acc);
            acc = fmaf(wp3, s3, acc);
            *(float*)(dc + (unsigned)(s * 32768)) = acc;   // lz += 2 per s
        }

        __syncthreads();             // WAR: window reused by next fill
    }
}

extern "C" void kernel_launch(void* const* d_in, const int* in_sizes, int n_in,
                              void* d_out, int out_size)
{
    const float* vol = (const float*)d_in[0];   // [8,16,64,64,64] f32
    const float* rot = (const float*)d_in[1];   // [8,3,3] f32
    float* out = (float*)d_out;

    cudaFuncSetAttribute(volrot_kernel,
                         cudaFuncAttributeMaxDynamicSharedMemorySize, WIN_BYTES);

    volrot_kernel<<<8 * 64, NTHR, WIN_BYTES>>>(vol, rot, out);
}

// round 13
// speedup vs baseline: 2.2864x; 2.2864x over previous
#include <cuda_runtime.h>
#include <cuda.h>

// VolumeRotation: B=8, C=16, S=64 — round 12: TMA staging (fixed) + fallback.
// TMA kernel: 16^3 tile, per channel ONE cp.async.bulk.tensor.4d loads the
// 32x29x29-float window (SW128 swizzle, HW zero-fill OOB) into a double
// buffer; 2-deep mbarrier pipeline. Fixes vs R11: bax 4-aligned (16B global
// alignment for the swizzled inner dim), rank-4 tensormap (b,c merged).
// Fallback kernel (encode failure): round-8 cp.async version (228us proven).

#define SB 64
#define CB 16
#define S3 (SB*SB*SB)
#define TT 16
#define NTHR 1024
#define SPT 4
#define WWN 29
#define NROWS (WWN*WWN)           // 841
#define WIN_BYTES (NROWS*128)     // 107648
#define WIN_STRIDE 108544         // 1024B multiple
#define SMEM_TMA (2*WIN_STRIDE + 1024)
#define SMEM_FB  (2*WIN_BYTES)    // fallback double buffer
#define SLOTS 7

__device__ __forceinline__ void sample_pos(
    float r00, float r01, float r02,
    float r10, float r11, float r12,
    float r20, float r21, float r22,
    int x, int y, int z,
    float& fx, float& fy, float& fz)
{
    const float sc = 2.0f / 63.0f;
    float bx = fmaf((float)x, sc, -1.0f);
    float by = fmaf((float)y, sc, -1.0f);
    float bz = fmaf((float)z, sc, -1.0f);
    float gx = fmaf(r00, bx, fmaf(r10, by, r20 * bz));
    float gy = fmaf(r01, bx, fmaf(r11, by, r21 * bz));
    float gz = fmaf(r02, bx, fmaf(r12, by, r22 * bz));
    fx = fmaf(gx, 32.0f, 31.5f);
    fy = fmaf(gy, 32.0f, 31.5f);
    fz = fmaf(gz, 32.0f, 31.5f);
}

#define MBAR_WAIT(bar, par) do {                                              \
    unsigned _done;                                                           \
    asm volatile("{\n\t.reg .pred p;\n\t"                                     \
        "mbarrier.try_wait.parity.acquire.cta.shared::cta.b64 p, [%1], %2;\n\t"\
        "selp.b32 %0, 1, 0, p;\n\t}"                                          \
        : "=r"(_done) : "r"(bar), "r"(par) : "memory");                       \
    if (!_done) {                                                             \
        asm volatile("{\n\t.reg .pred P1;\n\t"                                \
            "WL_%=:\n\t"                                                      \
            "mbarrier.try_wait.parity.acquire.cta.shared::cta.b64 P1, [%0], %1, 0x989680;\n\t" \
            "@P1 bra.uni WD_%=;\n\t"                                          \
            "bra.uni WL_%=;\n\t"                                              \
            "WD_%=:\n\t}"                                                     \
            :: "r"(bar), "r"(par) : "memory");                                \
    }                                                                         \
} while (0)

// ============================= TMA kernel ==================================

__global__ __launch_bounds__(NTHR, 1)
void volrot_tma(const __grid_constant__ CUtensorMap tmap,
                const float* __restrict__ rot,
                float* __restrict__ out)
{
    extern __shared__ float smemf[];
    __shared__ __align__(16) unsigned long long mbar[2];

    int tid = threadIdx.x;
    int blk = blockIdx.x;
    int b = blk >> 6;
    int t = blk & 63;
    int oz = (t >> 4) * TT;
    int oy = ((t >> 2) & 3) * TT;
    int ox = (t & 3) * TT;

    unsigned su_raw = (unsigned)__cvta_generic_to_shared(smemf);
    unsigned su = (su_raw + 1023u) & ~1023u;        // 1024B-aligned windows
    const char* wbase = (const char*)smemf + (su - su_raw);
    unsigned bar0 = (unsigned)__cvta_generic_to_shared(&mbar[0]);

    const float* R = rot + b * 9;
    float r00 = __ldg(R+0), r01 = __ldg(R+1), r02 = __ldg(R+2);
    float r10 = __ldg(R+3), r11 = __ldg(R+4), r12 = __ldg(R+5);
    float r20 = __ldg(R+6), r21 = __ldg(R+7), r22 = __ldg(R+8);

    float mnx = 1e30f, mny = 1e30f, mnz = 1e30f;
    #pragma unroll
    for (int k = 0; k < 8; k++) {
        int cx = ox + ((k & 1) ? TT - 1 : 0);
        int cy = oy + ((k & 2) ? TT - 1 : 0);
        int cz = oz + ((k & 4) ? TT - 1 : 0);
        float fx, fy, fz;
        sample_pos(r00,r01,r02,r10,r11,r12,r20,r21,r22, cx, cy, cz, fx, fy, fz);
        mnx = fminf(mnx, fx); mny = fminf(mny, fy); mnz = fminf(mnz, fz);
    }
    int bax = ((int)floorf(mnx)) & ~3;   // 16B-aligned inner-dim start (TMA req)
    int bay = (int)floorf(mny);
    int baz = (int)floorf(mnz);

    // per-sample channel-invariant state (TMA zero-fill => no validity masks)
    unsigned pk[SPT];
    float ex0[SPT], ex1[SPT], wp0[SPT], wp1[SPT], wp2[SPT], wp3[SPT];
    unsigned obyte0 = 0;

    #pragma unroll
    for (int s = 0; s < SPT; s++) {
        int v = tid + s * NTHR;
        int lx = v & 15, ly = (v >> 4) & 15, lz = v >> 8;
        int x = ox + lx, y = oy + ly, z = oz + lz;
        float fx, fy, fz;
        sample_pos(r00,r01,r02,r10,r11,r12,r20,r21,r22, x, y, z, fx, fy, fz);
        float x0f = floorf(fx), y0f = floorf(fy), z0f = floorf(fz);
        float tx = fx - x0f, ty = fy - y0f, tz = fz - z0f;
        int x0 = (int)x0f, y0 = (int)y0f, z0 = (int)z0f;

        ex0[s] = 1.0f - tx;  ex1[s] = tx;
        wp0[s] = (1.0f - ty) * (1.0f - tz);
        wp1[s] = ty * (1.0f - tz);
        wp2[s] = (1.0f - ty) * tz;
        wp3[s] = ty * tz;

        int wx0 = min(max(x0 - bax, 0), 30);
        int wy0 = min(max(y0 - bay, 0), WWN - 2);
        int wz0 = min(max(z0 - baz, 0), WWN - 2);
        unsigned rowid = (unsigned)(wz0 * WWN + wy0);
        unsigned ca0 = (unsigned)((((wx0    ) >> 2) << 4) | (((wx0    ) & 3) << 2));
        unsigned ca1 = (unsigned)((((wx0 + 1) >> 2) << 4) | (((wx0 + 1) & 3) << 2));
        pk[s] = rowid | (ca0 << 10) | (ca1 << 18);
        if (s == 0) obyte0 = (unsigned)((((z * SB) + y) * SB + x) * 4);
    }

    if (tid == 0) {
        asm volatile("mbarrier.init.shared.b64 [%0], 1;" :: "r"(bar0)     : "memory");
        asm volatile("mbarrier.init.shared.b64 [%0], 1;" :: "r"(bar0 + 8) : "memory");
    }
    __syncthreads();

    int wcoord = b * CB;     // merged (b,c) coordinate
    if (tid == 0) {
        #pragma unroll
        for (int c = 0; c < 2; c++) {
            unsigned bar = bar0 + 8u * (unsigned)c;
            asm volatile("mbarrier.arrive.expect_tx.shared.b64 _, [%0], %1;"
                :: "r"(bar), "r"((unsigned)WIN_BYTES) : "memory");
            asm volatile(
                "cp.async.bulk.tensor.4d.shared::cta.global.tile.mbarrier::complete_tx::bytes "
                "[%0], [%1, {%2, %3, %4, %5}], [%6];"
                :: "r"(su + (unsigned)c * (unsigned)WIN_STRIDE), "l"(&tmap),
                   "r"(bax), "r"(bay), "r"(baz), "r"(wcoord + c), "r"(bar)
                : "memory");
        }
    }

    char* dstb = (char*)out + (size_t)b * CB * S3 * 4;

    #pragma unroll 1
    for (int c = 0; c < CB; c++) {
        unsigned bar = bar0 + 8u * (unsigned)(c & 1);
        MBAR_WAIT(bar, (c >> 1) & 1);

        const char* wb = wbase + (unsigned)(c & 1) * (unsigned)WIN_STRIDE;
        char* dc = dstb + (size_t)c * S3 * 4 + obyte0;
        #pragma unroll
        for (int s = 0; s < SPT; s++) {
            unsigned p = pk[s];
            unsigned rowid = p & 1023u;
            unsigned ca0 = (p >> 10) & 0xFFu;
            unsigned ca1 = (p >> 18) & 0xFFu;

            unsigned rk0 = rowid * 128 + ((rowid & 7) << 4);
            unsigned rr1 = rowid + 1;
            unsigned rk1 = rr1 * 128 + ((rr1 & 7) << 4);
            unsigned rr2 = rowid + WWN;
            unsigned rk2 = rr2 * 128 + ((rr2 & 7) << 4);
            unsigned rr3 = rowid + WWN + 1;
            unsigned rk3 = rr3 * 128 + ((rr3 & 7) << 4);

            float v00 = *(const float*)(wb + (rk0 ^ ca0));
            float v01 = *(const float*)(wb + (rk0 ^ ca1));
            float v10 = *(const float*)(wb + (rk1 ^ ca0));
            float v11 = *(const float*)(wb + (rk1 ^ ca1));
            float v20 = *(const float*)(wb + (rk2 ^ ca0));
            float v21 = *(const float*)(wb + (rk2 ^ ca1));
            float v30 = *(const float*)(wb + (rk3 ^ ca0));
            float v31 = *(const float*)(wb + (rk3 ^ ca1));

            float s0 = fmaf(ex0[s], v00, ex1[s] * v01);
            float s1 = fmaf(ex0[s], v10, ex1[s] * v11);
            float s2 = fmaf(ex0[s], v20, ex1[s] * v21);
            float s3 = fmaf(ex0[s], v30, ex1[s] * v31);
            float acc = wp0[s] * s0;
            acc = fmaf(wp1[s], s1, acc);
            acc = fmaf(wp2[s], s2, acc);
            acc = fmaf(wp3[s], s3, acc);
            *(float*)(dc + (unsigned)(s * 65536)) = acc;
        }

        __syncthreads();   // buffer (c&1) fully consumed before refill
        if (c + 2 < CB && tid == 0) {
            asm volatile("mbarrier.arrive.expect_tx.shared.b64 _, [%0], %1;"
                :: "r"(bar), "r"((unsigned)WIN_BYTES) : "memory");
            asm volatile(
                "cp.async.bulk.tensor.4d.shared::cta.global.tile.mbarrier::complete_tx::bytes "
                "[%0], [%1, {%2, %3, %4, %5}], [%6];"
                :: "r"(su + (unsigned)(c & 1) * (unsigned)WIN_STRIDE), "l"(&tmap),
                   "r"(bax), "r"(bay), "r"(baz), "r"(wcoord + c + 2), "r"(bar)
                : "memory");
        }
    }
}

// ======================= Fallback kernel (round 8) =========================

__global__ __launch_bounds__(NTHR, 1)
void volrot_fb(const float* __restrict__ vol,
               const float* __restrict__ rot,
               float* __restrict__ out)
{
    extern __shared__ float smemf[];
    const char* wbase = (const char*)smemf;
    unsigned su = (unsigned)__cvta_generic_to_shared(smemf);

    int tid = threadIdx.x;
    int blk = blockIdx.x;
    int b = blk >> 6;
    int t = blk & 63;
    int oz = (t >> 4) * TT;
    int oy = ((t >> 2) & 3) * TT;
    int ox = (t & 3) * TT;

    const float* R = rot + b * 9;
    float r00 = __ldg(R+0), r01 = __ldg(R+1), r02 = __ldg(R+2);
    float r10 = __ldg(R+3), r11 = __ldg(R+4), r12 = __ldg(R+5);
    float r20 = __ldg(R+6), r21 = __ldg(R+7), r22 = __ldg(R+8);

    float mnx = 1e30f, mny = 1e30f, mnz = 1e30f;
    float mxx = -1e30f, mxy = -1e30f, mxz = -1e30f;
    #pragma unroll
    for (int k = 0; k < 8; k++) {
        int cx = ox + ((k & 1) ? TT - 1 : 0);
        int cy = oy + ((k & 2) ? TT - 1 : 0);
        int cz = oz + ((k & 4) ? TT - 1 : 0);
        float fx, fy, fz;
        sample_pos(r00,r01,r02,r10,r11,r12,r20,r21,r22, cx, cy, cz, fx, fy, fz);
        mnx = fminf(mnx, fx); mny = fminf(mny, fy); mnz = fminf(mnz, fz);
        mxx = fmaxf(mxx, fx); mxy = fmaxf(mxy, fy); mxz = fmaxf(mxz, fz);
    }
    int bax = ((int)floorf(mnx)) & ~3;
    int bay = (int)floorf(mny);
    int baz = (int)floorf(mnz);
    int exMax = ((int)floorf(mxx)) + 1 - bax;
    int eyMax = ((int)floorf(mxy)) + 1 - bay;
    int ezMax = ((int)floorf(mxz)) + 1 - baz;

    int xq = tid & 7;
    int r0 = tid >> 3;
    int gxq = bax + (xq << 2);
    unsigned need = 0, inb = 0;
    #pragma unroll
    for (int j = 0; j < SLOTS; j++) {
        int rowid = r0 + j * 128;
        if (rowid < NROWS) {
            int wz = rowid / WWN;
            int wy = rowid - wz * WWN;
            bool nd = ((xq << 2) <= exMax) & (wy <= eyMax) & (wz <= ezMax);
            int gy = bay + wy, gz = baz + wz;
            bool ok = ((unsigned)gxq <= (unsigned)(SB - 4)) &
                      ((unsigned)gy < (unsigned)SB) &
                      ((unsigned)gz < (unsigned)SB);
            if (nd) need |= (1u << j);
            if (ok) inb  |= (1u << j);
        }
    }
    unsigned sidx0 = (unsigned)(r0 * 128 + ((xq ^ (r0 & 7)) << 4));

    unsigned rpk[2], capk[2];
    float ex0[SPT], ex1[SPT], wp0[SPT], wp1[SPT], wp2[SPT], wp3[SPT];
    unsigned obyte0 = 0;
    rpk[0] = rpk[1] = capk[0] = capk[1] = 0;

    #pragma unroll
    for (int s = 0; s < SPT; s++) {
        int v = tid + s * NTHR;
        int lx = v & 15, ly = (v >> 4) & 15, lz = v >> 8;
        int x = ox + lx, y = oy + ly, z = oz + lz;
        float fx, fy, fz;
        sample_pos(r00,r01,r02,r10,r11,r12,r20,r21,r22, x, y, z, fx, fy, fz);
        float x0f = floorf(fx), y0f = floorf(fy), z0f = floorf(fz);
        float txf = fx - x0f, tyf = fy - y0f, tzf = fz - z0f;
        int x0 = (int)x0f, y0 = (int)y0f, z0 = (int)z0f;

        ex0[s] = ((unsigned)x0       < (unsigned)SB) ? (1.0f - txf) : 0.0f;
        ex1[s] = ((unsigned)(x0 + 1) < (unsigned)SB) ? txf          : 0.0f;
        bool vy0 = (unsigned)y0       < (unsigned)SB;
        bool vy1 = (unsigned)(y0 + 1) < (unsigned)SB;
        bool vz0 = (unsigned)z0       < (unsigned)SB;
        bool vz1 = (unsigned)(z0 + 1) < (unsigned)SB;
        wp0[s] = (vy0 && vz0) ? (1.0f - tyf) * (1.0f - tzf) : 0.0f;
        wp1[s] = (vy1 && vz0) ? tyf * (1.0f - tzf)          : 0.0f;
        wp2[s] = (vy0 && vz1) ? (1.0f - tyf) * tzf          : 0.0f;
        wp3[s] = (vy1 && vz1) ? tyf * tzf                   : 0.0f;

        int wx0 = min(max(x0 - bax, 0), 30);
        int wy0 = min(max(y0 - bay, 0), WWN - 2);
        int wz0 = min(max(z0 - baz, 0), WWN - 2);
        unsigned rowid = (unsigned)(wz0 * WWN + wy0);
        rpk[s >> 1] |= rowid << ((s & 1) * 16);
        int xa = wx0, xb = wx0 + 1;
        unsigned ca0 = (unsigned)(((xa >> 2) << 4) | ((xa & 3) << 2));
        unsigned ca1 = (unsigned)(((xb >> 2) << 4) | ((xb & 3) << 2));
        capk[s >> 1] |= (ca0 | (ca1 << 8)) << ((s & 1) * 16);
        if (s == 0) obyte0 = (unsigned)((((z * SB) + y) * SB + x) * 4);
    }

    const char* srcb = (const char*)vol + (size_t)b * CB * S3 * 4;
    char*       dstb = (char*)out       + (size_t)b * CB * S3 * 4;

    #define ISSUE_FILL(CH, BUFOFF)                                           \
    {                                                                        \
        const char* g = srcb + (size_t)(CH) * S3 * 4;                        \
        _Pragma("unroll")                                                    \
        for (int j = 0; j < SLOTS; j++) {                                    \
            if ((need >> j) & 1u) {                                          \
                int rowid = r0 + j * 128;                                    \
                int wz = rowid / WWN;                                        \
                int wy = rowid - wz * WWN;                                   \
                int gy = bay + wy, gz = baz + wz;                            \
                unsigned ok = (inb >> j) & 1u;                               \
                unsigned go = ok ? (unsigned)((((gz * SB) + gy) * SB + gxq) * 4) : 0u; \
                unsigned sz = ok << 4;                                       \
                asm volatile("cp.async.cg.shared.global [%0], [%1], 16, %2;" \
                    :: "r"(su + (BUFOFF) + sidx0 + (unsigned)(j * 16384)),   \
                       "l"(g + go), "r"(sz) : "memory");                     \
            }                                                                \
        }                                                                    \
        asm volatile("cp.async.commit_group;" ::: "memory");                 \
    }

    ISSUE_FILL(0, 0u);

    #pragma unroll 1
    for (int c = 0; c < CB; c++) {
        __syncthreads();

        if (c + 1 < CB) {
            unsigned nxtoff = ((c + 1) & 1) ? (unsigned)WIN_BYTES : 0u;
            ISSUE_FILL(c + 1, nxtoff);
            asm volatile("cp.async.wait_group 1;" ::: "memory");
        } else {
            asm volatile("cp.async.wait_group 0;" ::: "memory");
        }
        __syncthreads();

        const char* wb = wbase + ((c & 1) ? (unsigned)WIN_BYTES : 0u);
        char* dc = dstb + (size_t)c * S3 * 4 + obyte0;
        #pragma unroll
        for (int s = 0; s < SPT; s++) {
            unsigned rowid = (rpk[s >> 1] >> ((s & 1) * 16)) & 0xFFFFu;
            unsigned cap   = (capk[s >> 1] >> ((s & 1) * 16)) & 0xFFFFu;
            unsigned ca0 = cap & 0xFFu;
            unsigned ca1 = (cap >> 8) & 0xFFu;

            unsigned rk0 = rowid * 128 + ((rowid & 7) << 4);
            unsigned rr1 = rowid + 1;
            unsigned rk1 = rr1 * 128 + ((rr1 & 7) << 4);
            unsigned rr2 = rowid + WWN;
            unsigned rk2 = rr2 * 128 + ((rr2 & 7) << 4);
            unsigned rr3 = rowid + WWN + 1;
            unsigned rk3 = rr3 * 128 + ((rr3 & 7) << 4);

            float v00 = *(const float*)(wb + (rk0 ^ ca0));
            float v01 = *(const float*)(wb + (rk0 ^ ca1));
            float v10 = *(const float*)(wb + (rk1 ^ ca0));
            float v11 = *(const float*)(wb + (rk1 ^ ca1));
            float v20 = *(const float*)(wb + (rk2 ^ ca0));
            float v21 = *(const float*)(wb + (rk2 ^ ca1));
            float v30 = *(const float*)(wb + (rk3 ^ ca0));
            float v31 = *(const float*)(wb + (rk3 ^ ca1));

            float e0 = ex0[s], e1 = ex1[s];
            float s0 = fmaf(e0, v00, e1 * v01);
            float s1 = fmaf(e0, v10, e1 * v11);
            float s2 = fmaf(e0, v20, e1 * v21);
            float s3 = fmaf(e0, v30, e1 * v31);
            float acc = wp0[s] * s0;
            acc = fmaf(wp1[s], s1, acc);
            acc = fmaf(wp2[s], s2, acc);
            acc = fmaf(wp3[s], s3, acc);
            *(float*)(dc + (unsigned)(s * 65536)) = acc;
        }
    }
    #undef ISSUE_FILL
}

// ================================ host =====================================

extern "C" void kernel_launch(void* const* d_in, const int* in_sizes, int n_in,
                              void* d_out, int out_size)
{
    const float* vol = (const float*)d_in[0];
    const float* rot = (const float*)d_in[1];
    float* out = (float*)d_out;

    typedef CUresult (*EncodeFn)(
        CUtensorMap*, CUtensorMapDataType, cuuint32_t, void*,
        const cuuint64_t*, const cuuint64_t*, const cuuint32_t*,
        const cuuint32_t*, CUtensorMapInterleave, CUtensorMapSwizzle,
        CUtensorMapL2promotion, CUtensorMapFloatOOBfill);
    EncodeFn encode = nullptr;
#if CUDART_VERSION >= 12050
    cudaDriverEntryPointQueryResult qr;
    if (cudaGetDriverEntryPointByVersion("cuTensorMapEncodeTiled",
            (void**)&encode, 12000, cudaEnableDefault, &qr) != cudaSuccess ||
        qr != cudaDriverEntryPointSuccess)
        encode = nullptr;
#else
    if (cudaGetDriverEntryPoint("cuTensorMapEncodeTiled",
            (void**)&encode, cudaEnableDefault) != cudaSuccess)
        encode = nullptr;
#endif

    CUtensorMap tmap;
    __builtin_memset(&tmap, 0, sizeof(tmap));
    bool use_tma = false;
    if (encode) {
        cuuint64_t dims[4]    = {64, 64, 64, 128};          // x,y,z,(b*16+c)
        cuuint64_t strides[3] = {64ull * 4, 64ull * 64 * 4,
                                 64ull * 64 * 64 * 4};
        cuuint32_t box[4]     = {32, WWN, WWN, 1};
        cuuint32_t est[4]     = {1, 1, 1, 1};
        CUresult r = encode(&tmap, CU_TENSOR_MAP_DATA_TYPE_FLOAT32, 4,
                            (void*)vol, dims, strides, box, est,
                            CU_TENSOR_MAP_INTERLEAVE_NONE,
                            CU_TENSOR_MAP_SWIZZLE_128B,
                            CU_TENSOR_MAP_L2_PROMOTION_L2_128B,
                            CU_TENSOR_MAP_FLOAT_OOB_FILL_NONE);
        use_tma = (r == CUDA_SUCCESS);
    }

    if (use_tma) {
        cudaFuncSetAttribute(volrot_tma,
                             cudaFuncAttributeMaxDynamicSharedMemorySize, SMEM_TMA);
        volrot_tma<<<8 * 64, NTHR, SMEM_TMA>>>(tmap, rot, out);
    } else {
        cudaFuncSetAttribute(volrot_fb,
                             cudaFuncAttributeMaxDynamicSharedMemorySize, SMEM_FB);
        volrot_fb<<<8 * 64, NTHR, SMEM_FB>>>(vol, rot, out);
    }
}